// round 17
// baseline (speedup 1.0000x reference)
#include <cuda_runtime.h>

#define IH 4096
#define IW 4096
#define OH 4082
#define OW 4082

#define TILE_R 64          // output rows per block (2 rows per lane)
#define TILE_C 96          // output cols per block (6 warps x 16)
#define NTHR   192
#define IN_R   78          // TILE_R + 14 input rows staged
#define PITCH_F 128        // smem row pitch in floats
#define PITCH_B 512
#define LOAD_F4 28         // float4 per staged row

typedef unsigned long long ull;

__device__ __forceinline__ ull fma2(ull a, ull b, ull c) {
    ull d;
    asm("fma.rn.f32x2 %0, %1, %2, %3;" : "=l"(d) : "l"(a), "l"(b), "l"(c));
    return d;
}
__device__ __forceinline__ ull mkpair(unsigned lo, unsigned hi) {
    ull d;
    asm("mov.b64 %0, {%1, %2};" : "=l"(d) : "r"(lo), "r"(hi));
    return d;
}
__device__ __forceinline__ float lo_f(ull x) { return __uint_as_float((unsigned)x); }
__device__ __forceinline__ float hi_f(ull x) { return __uint_as_float((unsigned)(x >> 32)); }

// One weight row applied to the two phase-split accumulator sets.
// Weight row layout in smem (16 ulls): [0..7] = dup(w[2m]), [8..14] = dup(w[2m+1]).
// accE[p] (p=0..7): even-tap sums (e[2p], e[2p+1])   += a[p+m] * wE[m]
// accO[p] (p=0..8): odd-tap sums  (s[2p-1], s[2p])   += a[p+m] * wO[m]
// ALL operands are aligned pairs: zero pair-construction MOVs.
__device__ __forceinline__ void conv_row_p(ull* accE, ull* accO, const ull* a,
                                           const ull* __restrict__ wrow) {
#pragma unroll
    for (int m = 0; m < 8; ++m) {
        ull w = wrow[m];
#pragma unroll
        for (int p = 0; p < 8; ++p) accE[p] = fma2(a[p + m], w, accE[p]);
    }
#pragma unroll
    for (int m = 0; m < 7; ++m) {
        ull w = wrow[8 + m];
#pragma unroll
        for (int p = 0; p < 9; ++p) accO[p] = fma2(a[p + m], w, accO[p]);
    }
}

// Load 16 aligned window pairs (8 x LDS.128) for input row ir, 16B-XOR-swizzled.
__device__ __forceinline__ void load_win_p(const float* sA, int ir, int c0,
                                           ull* a) {
    const unsigned xv = (((unsigned)ir) >> 1) & 7u;
    const char* rowp = reinterpret_cast<const char*>(sA) + ir * PITCH_B;
#pragma unroll
    for (int i = 0; i < 8; ++i) {
        ulonglong2 t = *reinterpret_cast<const ulonglong2*>(
            rowp + ((unsigned)((c0 + i) ^ xv) << 4));
        a[2 * i] = t.x;
        a[2 * i + 1] = t.y;
    }
}

__global__ void __launch_bounds__(NTHR, 3)
conv15_kernel(const float* __restrict__ X, const float* __restrict__ Wt,
              const float* __restrict__ bias, float* __restrict__ out) {
    __shared__ float sA[IN_R * PITCH_F];
    __shared__ __align__(16) ull sW[15 * 16];  // row j: [0..7]=even taps, [8..14]=odd

    const int tid = threadIdx.x;
    const int gro = blockIdx.y * TILE_R;
    const int gco = blockIdx.x * TILE_C;

    // Stage weights as duplicated pairs, parity-split per row.
    for (int i = tid; i < 225; i += NTHR) {
        int row = i / 15;
        int t = i - row * 15;
        int slot = (t & 1) ? (8 + (t >> 1)) : (t >> 1);
        unsigned wb = __float_as_uint(Wt[i]);
        sW[row * 16 + slot] = mkpair(wb, wb);
    }

    // Stage the input tile with 16B-granularity XOR swizzle: chunk ^ ((row>>1)&7).
    for (int idx = tid; idx < IN_R * LOAD_F4; idx += NTHR) {
        int r = idx / LOAD_F4;
        int c4 = idx - r * LOAD_F4;
        int gr = gro + r;
        int gc = gco + c4 * 4;
        float4 v = make_float4(0.f, 0.f, 0.f, 0.f);
        if (gr < IH && gc < IW)
            v = *reinterpret_cast<const float4*>(X + (size_t)gr * IW + gc);
        unsigned xv = (((unsigned)r) >> 1) & 7u;
        *reinterpret_cast<float4*>(sA + r * PITCH_F + (((unsigned)c4 ^ xv) << 2)) = v;
    }
    __syncthreads();

    const int warp = tid >> 5;         // 0..5 -> 16-col strip
    const int lane = tid & 31;
    const int c0 = warp * 4;           // window base in 16B chunks
    const int r0 = lane * 2;           // two output rows per lane

    ull accE0[8], accO0[9], accE1[8], accO1[9];
#pragma unroll
    for (int p = 0; p < 8; ++p) { accE0[p] = 0ULL; accE1[p] = 0ULL; }
#pragma unroll
    for (int p = 0; p < 9; ++p) { accO0[p] = 0ULL; accO1[p] = 0ULL; }

    ull a[16];

    // row r0+j contributes to out-row r0 with w[j], to out-row r0+1 with w[j-1].

    // j = 0 : only row0 accs (w0).
    load_win_p(sA, r0, c0, a);
    conv_row_p(accE0, accO0, a, sW);

    // j = 1..14 : both output rows share the same window load.
#pragma unroll 1
    for (int j = 1; j <= 14; ++j) {
        load_win_p(sA, r0 + j, c0, a);
        conv_row_p(accE0, accO0, a, sW + j * 16);
        conv_row_p(accE1, accO1, a, sW + (j - 1) * 16);
    }

    // j = 15 : only row1 accs (w14).
    load_win_p(sA, r0 + 15, c0, a);
    conv_row_p(accE1, accO1, a, sW + 14 * 16);

    // Epilogue: recombine phases.
    //   out[2p]   = accE[p].lo + accO[p].hi  (+bias)
    //   out[2p+1] = accE[p].hi + accO[p+1].lo (+bias)
    const float bv = bias[0];
    const int oc0 = gco + warp * 16;

    {
        int orow = gro + r0;
        if (orow < OH) {
            float* op = out + (size_t)orow * OW;
#pragma unroll
            for (int p = 0; p < 8; ++p) {
                int oc = oc0 + 2 * p;
                if (oc < OW) {
                    float2 v;
                    v.x = lo_f(accE0[p]) + hi_f(accO0[p]) + bv;
                    v.y = hi_f(accE0[p]) + lo_f(accO0[p + 1]) + bv;
                    *reinterpret_cast<float2*>(op + oc) = v;
                }
            }
        }
    }
    {
        int orow = gro + r0 + 1;
        if (orow < OH) {
            float* op = out + (size_t)orow * OW;
#pragma unroll
            for (int p = 0; p < 8; ++p) {
                int oc = oc0 + 2 * p;
                if (oc < OW) {
                    float2 v;
                    v.x = lo_f(accE1[p]) + hi_f(accO1[p]) + bv;
                    v.y = hi_f(accE1[p]) + lo_f(accO1[p + 1]) + bv;
                    *reinterpret_cast<float2*>(op + oc) = v;
                }
            }
        }
    }
}

extern "C" void kernel_launch(void* const* d_in, const int* in_sizes, int n_in,
                              void* d_out, int out_size) {
    (void)in_sizes; (void)n_in; (void)out_size;
    const float* X = (const float*)d_in[0];
    const float* W = (const float*)d_in[1];
    const float* b = (const float*)d_in[2];
    float* out = (float*)d_out;

    cudaFuncSetAttribute(conv15_kernel,
                         cudaFuncAttributePreferredSharedMemoryCarveout,
                         cudaSharedmemCarveoutMaxShared);

    dim3 grid((OW + TILE_C - 1) / TILE_C, (OH + TILE_R - 1) / TILE_R);
    conv15_kernel<<<grid, NTHR>>>(X, W, b, out);
}